// round 3
// baseline (speedup 1.0000x reference)
#include <cuda_runtime.h>
#include <cuda_bf16.h>
#include <math.h>

// ---------------------------------------------------------------------------
// Problem constants
// ---------------------------------------------------------------------------
#define NMAX 50000
#define EMAX 800000
#define F_IN 256
#define HDIM 128
#define DDIM 64
#define PDIM 512   // 8 projections x 64

// Packed projection offsets within a row of P
#define OFF_QMU 0
#define OFF_KMU 64
#define OFF_VMU 128
#define OFF_SMU 192
#define OFF_QLS 256
#define OFF_KLS 320
#define OFF_VLS 384
#define OFF_SLS 448

// ---------------------------------------------------------------------------
// Static device scratch (no cudaMalloc allowed)
// ---------------------------------------------------------------------------
__device__ int   g_is64;
__device__ int   g_cnt[NMAX];
__device__ int   g_rowptr[NMAX + 1];
__device__ int   g_cursor[NMAX];
__device__ int   g_src32[EMAX];
__device__ int   g_dst32[EMAX];
__device__ int   g_csr_src[EMAX];
__device__ float g_dinv[NMAX];
__device__ float g_h0[(size_t)NMAX * HDIM];   // x @ W_gcn
__device__ float g_h [(size_t)NMAX * HDIM];   // after agg + bias + leaky
__device__ float g_P [(size_t)NMAX * PDIM];   // packed q/k/v/s for mu & ls
__device__ float g_Wcat[HDIM * PDIM];
__device__ float g_bcat[PDIM];

// ---------------------------------------------------------------------------
// Edge dtype detection: int64 edge_index has zero high words; int32 data has
// random node ids in the odd word positions.
// ---------------------------------------------------------------------------
__global__ void detect_dtype_kernel(const int* __restrict__ w, int e) {
    __shared__ int s[256];
    int t = threadIdx.x;
    int limit = (e < 256) ? e : 256;
    int nz = 0;
    if (t < limit) nz = (w[2 * t + 1] != 0) ? 1 : 0;
    s[t] = nz;
    __syncthreads();
    for (int o = 128; o; o >>= 1) {
        if (t < o) s[t] += s[t + o];
        __syncthreads();
    }
    if (t == 0) g_is64 = (s[0] == 0) ? 1 : 0;
}

// ---------------------------------------------------------------------------
// Small prep kernels
// ---------------------------------------------------------------------------
__global__ void zero_cnt_kernel(int n) {
    int i = blockIdx.x * blockDim.x + threadIdx.x;
    if (i < n) g_cnt[i] = 0;
}

__global__ void edge_prep_kernel(const void* __restrict__ ei, int e, int n) {
    int idx = blockIdx.x * blockDim.x + threadIdx.x;
    if (idx >= e) return;
    int s, d;
    if (g_is64) {
        const long long* p = (const long long*)ei;
        s = (int)p[idx];
        d = (int)p[idx + e];
    } else {
        const int* p = (const int*)ei;
        s = p[idx];
        d = p[idx + e];
    }
    // defensive clamp (never triggers on valid data; prevents aperture traps)
    s = (s < 0) ? 0 : ((s >= n) ? n - 1 : s);
    d = (d < 0) ? 0 : ((d >= n) ? n - 1 : d);
    g_src32[idx] = s;
    g_dst32[idx] = d;
    atomicAdd(&g_cnt[d], 1);
}

// Single-block exclusive scan over cnt -> rowptr/cursor, plus dinv.
__global__ void scan_kernel(int n) {
    const int T = 1024;
    int t = threadIdx.x;
    int per = (n + T - 1) / T;
    int start = t * per;
    int end = start + per; if (end > n) end = n;

    int sum = 0;
    for (int i = start; i < end; ++i) sum += g_cnt[i];

    __shared__ int ssum[T];
    ssum[t] = sum;
    __syncthreads();
    // inclusive Hillis-Steele
    for (int off = 1; off < T; off <<= 1) {
        int v = 0;
        if (t >= off) v = ssum[t - off];
        __syncthreads();
        if (t >= off) ssum[t] += v;
        __syncthreads();
    }
    int run = (t == 0) ? 0 : ssum[t - 1];
    for (int i = start; i < end; ++i) {
        g_rowptr[i] = run;
        g_cursor[i] = run;
        run += g_cnt[i];
        g_dinv[i] = rsqrtf((float)(g_cnt[i] + 1));  // +1 self loop; deg >= 1 always
    }
    if (t == T - 1) g_rowptr[n] = ssum[T - 1];
}

__global__ void fill_csr_kernel(int e) {
    int idx = blockIdx.x * blockDim.x + threadIdx.x;
    if (idx >= e) return;
    int d = g_dst32[idx];
    int pos = atomicAdd(&g_cursor[d], 1);
    g_csr_src[pos] = g_src32[idx];
}

__global__ void pack_weights_kernel(
    const float* W0, const float* W1, const float* W2, const float* W3,
    const float* W4, const float* W5, const float* W6, const float* W7,
    const float* b0, const float* b1, const float* b2, const float* b3,
    const float* b4, const float* b5, const float* b6, const float* b7) {
    const float* Ws[8] = {W0, W1, W2, W3, W4, W5, W6, W7};
    const float* bs[8] = {b0, b1, b2, b3, b4, b5, b6, b7};
    int idx = blockIdx.x * blockDim.x + threadIdx.x;
    if (idx < HDIM * PDIM) {
        int k = idx / PDIM;
        int j = idx % PDIM;
        int p = j / DDIM;
        int c = j % DDIM;
        g_Wcat[idx] = Ws[p][k * DDIM + c];
    }
    if (idx < PDIM) {
        g_bcat[idx] = bs[idx / DDIM][idx % DDIM];
    }
}

// ---------------------------------------------------------------------------
// SGEMM core: C[M,NC] = A[M,K] @ B[K,NC] (+bias). BM=64, BN=64, BK=32,
// 256 threads, 4x4 micro-tile per thread. K%32==0, NC%64==0; M ragged.
// ---------------------------------------------------------------------------
#define BM 64
#define BN 64
#define BK 32
#define AS_PAD 4

__device__ __forceinline__ void sgemm_core(
    const float* __restrict__ A, const float* __restrict__ B,
    const float* __restrict__ bias, float* __restrict__ C,
    int M, int K, int NC) {
    __shared__ float As[BK][BM + AS_PAD];   // transposed A tile
    __shared__ float Bs[BK][BN];

    int t = threadIdx.x;
    int tx = t & 15;        // col group 0..15
    int ty = t >> 4;        // row group 0..15
    int rowBlock = blockIdx.y * BM;
    int colBlock = blockIdx.x * BN;

    float acc[4][4] = {};

    for (int k0 = 0; k0 < K; k0 += BK) {
        // Load A tile (BM x BK = 2048 floats = 512 float4; 2 per thread)
        #pragma unroll
        for (int l = 0; l < 2; ++l) {
            int lin = t + l * 256;            // float4 index
            int ar = lin >> 3;                // BK/4 = 8 float4 per row
            int ac = (lin & 7) << 2;
            float4 v = make_float4(0.f, 0.f, 0.f, 0.f);
            int grow = rowBlock + ar;
            if (grow < M)
                v = *(const float4*)&A[(size_t)grow * K + k0 + ac];
            As[ac + 0][ar] = v.x;
            As[ac + 1][ar] = v.y;
            As[ac + 2][ar] = v.z;
            As[ac + 3][ar] = v.w;
        }
        // Load B tile (BK x BN = 2048 floats)
        #pragma unroll
        for (int l = 0; l < 2; ++l) {
            int lin = t + l * 256;
            int br = lin >> 4;                // BN/4 = 16 float4 per row
            int bc = (lin & 15) << 2;
            *(float4*)&Bs[br][bc] =
                *(const float4*)&B[(size_t)(k0 + br) * NC + colBlock + bc];
        }
        __syncthreads();

        #pragma unroll
        for (int kk = 0; kk < BK; ++kk) {
            float4 a4 = *(const float4*)&As[kk][ty * 4];
            float4 b4 = *(const float4*)&Bs[kk][tx * 4];
            float a[4] = {a4.x, a4.y, a4.z, a4.w};
            float b[4] = {b4.x, b4.y, b4.z, b4.w};
            #pragma unroll
            for (int i = 0; i < 4; ++i)
                #pragma unroll
                for (int j = 0; j < 4; ++j)
                    acc[i][j] = fmaf(a[i], b[j], acc[i][j]);
        }
        __syncthreads();
    }

    #pragma unroll
    for (int i = 0; i < 4; ++i) {
        int grow = rowBlock + ty * 4 + i;
        if (grow >= M) continue;
        int gcol = colBlock + tx * 4;
        float4 o;
        o.x = acc[i][0]; o.y = acc[i][1]; o.z = acc[i][2]; o.w = acc[i][3];
        if (bias) {
            float4 bb = *(const float4*)&bias[gcol];
            o.x += bb.x; o.y += bb.y; o.z += bb.z; o.w += bb.w;
        }
        *(float4*)&C[(size_t)grow * NC + gcol] = o;
    }
}

__global__ __launch_bounds__(256) void sgemm_xw_kernel(
    const float* __restrict__ A, const float* __restrict__ B, int M) {
    sgemm_core(A, B, nullptr, g_h0, M, F_IN, HDIM);
}

__global__ __launch_bounds__(256) void sgemm_proj_kernel(int M) {
    sgemm_core(g_h, g_Wcat, g_bcat, g_P, M, HDIM, PDIM);
}

// ---------------------------------------------------------------------------
// GCN aggregate: one warp per node. acc = sum_{e: dst=i} dinv[src]*dinv[i]*h0[src]
//                + dinv[i]^2 * h0[i] + b, then LeakyReLU(0.01).
// ---------------------------------------------------------------------------
__global__ void gcn_agg_kernel(const float* __restrict__ bias, int n) {
    int warp = (blockIdx.x * blockDim.x + threadIdx.x) >> 5;
    int lane = threadIdx.x & 31;
    if (warp >= n) return;
    int i = warp;
    float di = g_dinv[i];

    float4 acc = make_float4(0.f, 0.f, 0.f, 0.f);
    int e0 = g_rowptr[i], e1 = g_rowptr[i + 1];
    for (int e = e0; e < e1; ++e) {
        int src = g_csr_src[e];
        float w = g_dinv[src] * di;
        float4 v = *(const float4*)&g_h0[(size_t)src * HDIM + lane * 4];
        acc.x = fmaf(w, v.x, acc.x);
        acc.y = fmaf(w, v.y, acc.y);
        acc.z = fmaf(w, v.z, acc.z);
        acc.w = fmaf(w, v.w, acc.w);
    }
    // self loop
    {
        float w = di * di;
        float4 v = *(const float4*)&g_h0[(size_t)i * HDIM + lane * 4];
        acc.x = fmaf(w, v.x, acc.x);
        acc.y = fmaf(w, v.y, acc.y);
        acc.z = fmaf(w, v.z, acc.z);
        acc.w = fmaf(w, v.w, acc.w);
    }
    float4 bb = *(const float4*)&bias[lane * 4];
    acc.x += bb.x; acc.y += bb.y; acc.z += bb.z; acc.w += bb.w;
    // LeakyReLU(0.01)
    acc.x = (acc.x >= 0.f) ? acc.x : 0.01f * acc.x;
    acc.y = (acc.y >= 0.f) ? acc.y : 0.01f * acc.y;
    acc.z = (acc.z >= 0.f) ? acc.z : 0.01f * acc.z;
    acc.w = (acc.w >= 0.f) ? acc.w : 0.01f * acc.w;
    *(float4*)&g_h[(size_t)i * HDIM + lane * 4] = acc;
}

// ---------------------------------------------------------------------------
// Fused TransformerConv (mu + logstd): one warp per dst node, online softmax.
// ---------------------------------------------------------------------------
__global__ void transformer_kernel(float* __restrict__ out, int n) {
    int warp = (blockIdx.x * blockDim.x + threadIdx.x) >> 5;
    int lane = threadIdx.x & 31;
    if (warp >= n) return;
    int i = warp;
    const float* Pi = &g_P[(size_t)i * PDIM];

    float qm0 = Pi[OFF_QMU + lane], qm1 = Pi[OFF_QMU + 32 + lane];
    float ql0 = Pi[OFF_QLS + lane], ql1 = Pi[OFF_QLS + 32 + lane];

    float mm = -INFINITY, ml = -INFINITY;
    float sm = 0.f, sl = 0.f;
    float am0 = 0.f, am1 = 0.f, al0 = 0.f, al1 = 0.f;

    int e0 = g_rowptr[i], e1 = g_rowptr[i + 1];
    for (int e = e0; e < e1; ++e) {
        int src = g_csr_src[e];
        const float* Ps = &g_P[(size_t)src * PDIM];

        float pm = qm0 * Ps[OFF_KMU + lane] + qm1 * Ps[OFF_KMU + 32 + lane];
        float pl = ql0 * Ps[OFF_KLS + lane] + ql1 * Ps[OFF_KLS + 32 + lane];
        #pragma unroll
        for (int off = 16; off; off >>= 1) {
            pm += __shfl_xor_sync(0xffffffffu, pm, off);
            pl += __shfl_xor_sync(0xffffffffu, pl, off);
        }
        float alm = pm * 0.125f;   // / sqrt(64)
        float all = pl * 0.125f;

        float vm0 = Ps[OFF_VMU + lane], vm1 = Ps[OFF_VMU + 32 + lane];
        float vl0 = Ps[OFF_VLS + lane], vl1 = Ps[OFF_VLS + 32 + lane];

        // mu online softmax
        {
            float nm = fmaxf(mm, alm);
            float scale = __expf(mm - nm);    // expf(-inf)=0 on first edge
            float p = __expf(alm - nm);
            sm = sm * scale + p;
            am0 = am0 * scale + p * vm0;
            am1 = am1 * scale + p * vm1;
            mm = nm;
        }
        // logstd online softmax
        {
            float nm = fmaxf(ml, all);
            float scale = __expf(ml - nm);
            float p = __expf(all - nm);
            sl = sl * scale + p;
            al0 = al0 * scale + p * vl0;
            al1 = al1 * scale + p * vl1;
            ml = nm;
        }
    }

    size_t nd = (size_t)n * DDIM;
    float om0 = am0 / (sm + 1e-16f) + Pi[OFF_SMU + lane];
    float om1 = am1 / (sm + 1e-16f) + Pi[OFF_SMU + 32 + lane];
    out[(size_t)i * DDIM + lane]      = om0;
    out[(size_t)i * DDIM + 32 + lane] = om1;

    float ol0 = fminf(al0 / (sl + 1e-16f) + Pi[OFF_SLS + lane], 10.0f);
    float ol1 = fminf(al1 / (sl + 1e-16f) + Pi[OFF_SLS + 32 + lane], 10.0f);
    out[nd + (size_t)i * DDIM + lane]      = ol0;
    out[nd + (size_t)i * DDIM + 32 + lane] = ol1;
}

// ---------------------------------------------------------------------------
// Launch
// ---------------------------------------------------------------------------
extern "C" void kernel_launch(void* const* d_in, const int* in_sizes, int n_in,
                              void* d_out, int out_size) {
    const float*      x     = (const float*)d_in[0];
    const void*       ei    = (const void*)d_in[1];
    const float*      W_gcn = (const float*)d_in[2];
    const float*      b_gcn = (const float*)d_in[3];
    const float* Wq_mu = (const float*)d_in[4];  const float* bq_mu = (const float*)d_in[5];
    const float* Wk_mu = (const float*)d_in[6];  const float* bk_mu = (const float*)d_in[7];
    const float* Wv_mu = (const float*)d_in[8];  const float* bv_mu = (const float*)d_in[9];
    const float* Ws_mu = (const float*)d_in[10]; const float* bs_mu = (const float*)d_in[11];
    const float* Wq_ls = (const float*)d_in[12]; const float* bq_ls = (const float*)d_in[13];
    const float* Wk_ls = (const float*)d_in[14]; const float* bk_ls = (const float*)d_in[15];
    const float* Wv_ls = (const float*)d_in[16]; const float* bv_ls = (const float*)d_in[17];
    const float* Ws_ls = (const float*)d_in[18]; const float* bs_ls = (const float*)d_in[19];
    float* out = (float*)d_out;

    int n = in_sizes[0] / F_IN;      // 50000
    int e = in_sizes[1] / 2;         // 800000 (element count is dtype-independent)

    // 0) Detect edge_index dtype (int32 vs int64)
    detect_dtype_kernel<<<1, 256>>>((const int*)ei, e);

    // 1) CSR build
    zero_cnt_kernel<<<(n + 255) / 256, 256>>>(n);
    edge_prep_kernel<<<(e + 255) / 256, 256>>>(ei, e, n);
    scan_kernel<<<1, 1024>>>(n);
    fill_csr_kernel<<<(e + 255) / 256, 256>>>(e);

    // 2) Pack projection weights (order: qmu,kmu,vmu,smu,qls,kls,vls,sls)
    pack_weights_kernel<<<(HDIM * PDIM + 255) / 256, 256>>>(
        Wq_mu, Wk_mu, Wv_mu, Ws_mu, Wq_ls, Wk_ls, Wv_ls, Ws_ls,
        bq_mu, bk_mu, bv_mu, bs_mu, bq_ls, bk_ls, bv_ls, bs_ls);

    // 3) h0 = x @ W_gcn    [n,256]@[256,128]
    {
        dim3 grid(HDIM / BN, (n + BM - 1) / BM);
        sgemm_xw_kernel<<<grid, 256>>>(x, W_gcn, n);
    }

    // 4) GCN aggregate + bias + LeakyReLU -> h
    gcn_agg_kernel<<<(n + 7) / 8, 256>>>(b_gcn, n);

    // 5) P = h @ Wcat + bcat    [n,128]@[128,512]
    {
        dim3 grid(PDIM / BN, (n + BM - 1) / BM);
        sgemm_proj_kernel<<<grid, 256>>>(n);
    }

    // 6) Fused TransformerConv (mu + logstd) -> out
    transformer_kernel<<<(n + 7) / 8, 256>>>(out, n);
}

// round 4
// speedup vs baseline: 1.2858x; 1.2858x over previous
#include <cuda_runtime.h>
#include <cuda_bf16.h>
#include <math.h>

// ---------------------------------------------------------------------------
// Problem constants
// ---------------------------------------------------------------------------
#define NMAX 50000
#define EMAX 800000
#define F_IN 256
#define HDIM 128
#define DDIM 64
#define PDIM 512   // 8 projections x 64

// Packed projection offsets within a row of P.
// q/skip block first (read once per dst node), k/v block contiguous last
// (gathered 1KB per edge -> full-line sectors).
#define OFF_QMU 0
#define OFF_SMU 64
#define OFF_QLS 128
#define OFF_SLS 192
#define OFF_KMU 256
#define OFF_VMU 320
#define OFF_KLS 384
#define OFF_VLS 448

// ---------------------------------------------------------------------------
// Static device scratch (no cudaMalloc allowed)
// ---------------------------------------------------------------------------
__device__ int   g_is64;
__device__ int   g_cnt[NMAX];
__device__ int   g_pref[NMAX];
__device__ int   g_bsum[64];
__device__ int   g_rowptr[NMAX + 1];
__device__ int   g_cursor[NMAX];
__device__ int   g_src32[EMAX];
__device__ int   g_dst32[EMAX];
__device__ int   g_csr_src[EMAX];
__device__ float g_dinv[NMAX];
__device__ float g_h0[(size_t)NMAX * HDIM];   // x @ W_gcn
__device__ float g_h [(size_t)NMAX * HDIM];   // after agg + bias + leaky
__device__ float g_P [(size_t)NMAX * PDIM];   // packed projections
__device__ float g_Wcat[HDIM * PDIM];
__device__ float g_bcat[PDIM];

// ---------------------------------------------------------------------------
// Edge dtype detection: int64 edge_index has zero high words.
// ---------------------------------------------------------------------------
__global__ void detect_dtype_kernel(const int* __restrict__ w, int e) {
    __shared__ int s[256];
    int t = threadIdx.x;
    int limit = (e < 256) ? e : 256;
    int nz = 0;
    if (t < limit) nz = (w[2 * t + 1] != 0) ? 1 : 0;
    s[t] = nz;
    __syncthreads();
    for (int o = 128; o; o >>= 1) {
        if (t < o) s[t] += s[t + o];
        __syncthreads();
    }
    if (t == 0) g_is64 = (s[0] == 0) ? 1 : 0;
}

__global__ void zero_cnt_kernel(int n) {
    int i = blockIdx.x * blockDim.x + threadIdx.x;
    if (i < n) g_cnt[i] = 0;
}

__global__ void edge_prep_kernel(const void* __restrict__ ei, int e, int n) {
    int idx = blockIdx.x * blockDim.x + threadIdx.x;
    if (idx >= e) return;
    int s, d;
    if (g_is64) {
        const long long* p = (const long long*)ei;
        s = (int)p[idx];
        d = (int)p[idx + e];
    } else {
        const int* p = (const int*)ei;
        s = p[idx];
        d = p[idx + e];
    }
    s = (s < 0) ? 0 : ((s >= n) ? n - 1 : s);
    d = (d < 0) ? 0 : ((d >= n) ? n - 1 : d);
    g_src32[idx] = s;
    g_dst32[idx] = d;
    atomicAdd(&g_cnt[d], 1);
}

// ---------------------------------------------------------------------------
// Parallel scan, 2 passes. Pass 1: per-block (1024) inclusive scan + block sum.
// Pass 2: each block accumulates preceding block sums (<=49), writes
// rowptr/cursor/dinv, all coalesced.
// ---------------------------------------------------------------------------
__global__ void scan_pass1_kernel(int n) {
    __shared__ int s[1024];
    int t = threadIdx.x;
    int i = blockIdx.x * 1024 + t;
    int v = (i < n) ? g_cnt[i] : 0;
    s[t] = v;
    __syncthreads();
    #pragma unroll
    for (int off = 1; off < 1024; off <<= 1) {
        int u = 0;
        if (t >= off) u = s[t - off];
        __syncthreads();
        if (t >= off) s[t] += u;
        __syncthreads();
    }
    if (i < n) g_pref[i] = s[t];
    if (t == 1023) g_bsum[blockIdx.x] = s[t];
}

__global__ void scan_pass2_kernel(int n) {
    __shared__ int sboff;
    int b = blockIdx.x;
    int t = threadIdx.x;
    if (t == 0) {
        int acc = 0;
        for (int j = 0; j < b; ++j) acc += g_bsum[j];
        sboff = acc;
    }
    __syncthreads();
    int i = b * 1024 + t;
    if (i < n) {
        int incl = g_pref[i] + sboff;
        int c = g_cnt[i];
        int excl = incl - c;
        g_rowptr[i] = excl;
        g_cursor[i] = excl;
        g_dinv[i] = rsqrtf((float)(c + 1));
        if (i == n - 1) g_rowptr[n] = incl;
    }
}

__global__ void fill_csr_kernel(int e) {
    int idx = blockIdx.x * blockDim.x + threadIdx.x;
    if (idx >= e) return;
    int d = g_dst32[idx];
    int pos = atomicAdd(&g_cursor[d], 1);
    g_csr_src[pos] = g_src32[idx];
}

// Pointer order matches packed offsets: qmu,smu,qls,sls,kmu,vmu,kls,vls
__global__ void pack_weights_kernel(
    const float* W0, const float* W1, const float* W2, const float* W3,
    const float* W4, const float* W5, const float* W6, const float* W7,
    const float* b0, const float* b1, const float* b2, const float* b3,
    const float* b4, const float* b5, const float* b6, const float* b7) {
    const float* Ws[8] = {W0, W1, W2, W3, W4, W5, W6, W7};
    const float* bs[8] = {b0, b1, b2, b3, b4, b5, b6, b7};
    int idx = blockIdx.x * blockDim.x + threadIdx.x;
    if (idx < HDIM * PDIM) {
        int k = idx / PDIM;
        int j = idx % PDIM;
        int p = j / DDIM;
        int c = j % DDIM;
        g_Wcat[idx] = Ws[p][k * DDIM + c];
    }
    if (idx < PDIM) {
        g_bcat[idx] = bs[idx / DDIM][idx % DDIM];
    }
}

// ---------------------------------------------------------------------------
// SGEMM core: C[M,NC] = A[M,K] @ B[K,NC] (+bias).
// BM=128, BN=128, BK=16, 256 threads, 8x8 micro-tile.
// K % 16 == 0, NC % 128 == 0; M ragged (guarded).
// ---------------------------------------------------------------------------
#define BM 128
#define BN 128
#define BK 16
#define AS_PAD 4

__device__ __forceinline__ void sgemm_core(
    const float* __restrict__ A, const float* __restrict__ B,
    const float* __restrict__ bias, float* __restrict__ C,
    int M, int K, int NC) {
    __shared__ float As[BK][BM + AS_PAD];   // transposed A tile
    __shared__ float Bs[BK][BN];

    int t = threadIdx.x;
    int tx = t & 15;        // 0..15 -> col group
    int ty = t >> 4;        // 0..15 -> row group
    int rowBlock = blockIdx.y * BM;
    int colBlock = blockIdx.x * BN;

    float acc[8][8] = {};

    for (int k0 = 0; k0 < K; k0 += BK) {
        // A tile: BM x BK = 2048 floats = 512 float4; 2 per thread
        #pragma unroll
        for (int l = 0; l < 2; ++l) {
            int lin = t + l * 256;            // float4 index 0..511
            int ar = lin >> 2;                // row 0..127
            int ac = (lin & 3) << 2;          // col 0,4,8,12
            float4 v = make_float4(0.f, 0.f, 0.f, 0.f);
            int grow = rowBlock + ar;
            if (grow < M)
                v = *(const float4*)&A[(size_t)grow * K + k0 + ac];
            As[ac + 0][ar] = v.x;
            As[ac + 1][ar] = v.y;
            As[ac + 2][ar] = v.z;
            As[ac + 3][ar] = v.w;
        }
        // B tile: BK x BN = 2048 floats
        #pragma unroll
        for (int l = 0; l < 2; ++l) {
            int lin = t + l * 256;
            int br = lin >> 5;                // row 0..15
            int bc = (lin & 31) << 2;         // col 0..124
            *(float4*)&Bs[br][bc] =
                *(const float4*)&B[(size_t)(k0 + br) * NC + colBlock + bc];
        }
        __syncthreads();

        #pragma unroll
        for (int kk = 0; kk < BK; ++kk) {
            float a[8], b[8];
            *(float4*)&a[0] = *(const float4*)&As[kk][ty * 8];
            *(float4*)&a[4] = *(const float4*)&As[kk][ty * 8 + 4];
            *(float4*)&b[0] = *(const float4*)&Bs[kk][tx * 8];
            *(float4*)&b[4] = *(const float4*)&Bs[kk][tx * 8 + 4];
            #pragma unroll
            for (int i = 0; i < 8; ++i)
                #pragma unroll
                for (int j = 0; j < 8; ++j)
                    acc[i][j] = fmaf(a[i], b[j], acc[i][j]);
        }
        __syncthreads();
    }

    #pragma unroll
    for (int i = 0; i < 8; ++i) {
        int grow = rowBlock + ty * 8 + i;
        if (grow >= M) continue;
        int gcol = colBlock + tx * 8;
        float o[8];
        #pragma unroll
        for (int j = 0; j < 8; ++j) o[j] = acc[i][j];
        if (bias) {
            #pragma unroll
            for (int j = 0; j < 8; ++j) o[j] += bias[gcol + j];
        }
        *(float4*)&C[(size_t)grow * NC + gcol]     = *(float4*)&o[0];
        *(float4*)&C[(size_t)grow * NC + gcol + 4] = *(float4*)&o[4];
    }
}

__global__ __launch_bounds__(256) void sgemm_xw_kernel(
    const float* __restrict__ A, const float* __restrict__ B, int M) {
    sgemm_core(A, B, nullptr, g_h0, M, F_IN, HDIM);
}

__global__ __launch_bounds__(256) void sgemm_proj_kernel(int M) {
    sgemm_core(g_h, g_Wcat, g_bcat, g_P, M, HDIM, PDIM);
}

// ---------------------------------------------------------------------------
// GCN aggregate: one warp per node.
// ---------------------------------------------------------------------------
__global__ void gcn_agg_kernel(const float* __restrict__ bias, int n) {
    int warp = (blockIdx.x * blockDim.x + threadIdx.x) >> 5;
    int lane = threadIdx.x & 31;
    if (warp >= n) return;
    int i = warp;
    float di = g_dinv[i];

    float4 acc = make_float4(0.f, 0.f, 0.f, 0.f);
    int e0 = g_rowptr[i], e1 = g_rowptr[i + 1];
    for (int e = e0; e < e1; ++e) {
        int src = g_csr_src[e];
        float w = g_dinv[src] * di;
        float4 v = *(const float4*)&g_h0[(size_t)src * HDIM + lane * 4];
        acc.x = fmaf(w, v.x, acc.x);
        acc.y = fmaf(w, v.y, acc.y);
        acc.z = fmaf(w, v.z, acc.z);
        acc.w = fmaf(w, v.w, acc.w);
    }
    {   // self loop
        float w = di * di;
        float4 v = *(const float4*)&g_h0[(size_t)i * HDIM + lane * 4];
        acc.x = fmaf(w, v.x, acc.x);
        acc.y = fmaf(w, v.y, acc.y);
        acc.z = fmaf(w, v.z, acc.z);
        acc.w = fmaf(w, v.w, acc.w);
    }
    float4 bb = *(const float4*)&bias[lane * 4];
    acc.x += bb.x; acc.y += bb.y; acc.z += bb.z; acc.w += bb.w;
    acc.x = (acc.x >= 0.f) ? acc.x : 0.01f * acc.x;
    acc.y = (acc.y >= 0.f) ? acc.y : 0.01f * acc.y;
    acc.z = (acc.z >= 0.f) ? acc.z : 0.01f * acc.z;
    acc.w = (acc.w >= 0.f) ? acc.w : 0.01f * acc.w;
    *(float4*)&g_h[(size_t)i * HDIM + lane * 4] = acc;
}

// ---------------------------------------------------------------------------
// Fused TransformerConv (mu + logstd): one warp per dst node, online softmax.
// ---------------------------------------------------------------------------
__global__ void transformer_kernel(float* __restrict__ out, int n) {
    int warp = (blockIdx.x * blockDim.x + threadIdx.x) >> 5;
    int lane = threadIdx.x & 31;
    if (warp >= n) return;
    int i = warp;
    const float* Pi = &g_P[(size_t)i * PDIM];

    float qm0 = Pi[OFF_QMU + lane], qm1 = Pi[OFF_QMU + 32 + lane];
    float ql0 = Pi[OFF_QLS + lane], ql1 = Pi[OFF_QLS + 32 + lane];

    float mm = -INFINITY, ml = -INFINITY;
    float sm = 0.f, sl = 0.f;
    float am0 = 0.f, am1 = 0.f, al0 = 0.f, al1 = 0.f;

    int e0 = g_rowptr[i], e1 = g_rowptr[i + 1];
    for (int e = e0; e < e1; ++e) {
        int src = g_csr_src[e];
        const float* Ps = &g_P[(size_t)src * PDIM];

        float pm = qm0 * Ps[OFF_KMU + lane] + qm1 * Ps[OFF_KMU + 32 + lane];
        float pl = ql0 * Ps[OFF_KLS + lane] + ql1 * Ps[OFF_KLS + 32 + lane];
        #pragma unroll
        for (int off = 16; off; off >>= 1) {
            pm += __shfl_xor_sync(0xffffffffu, pm, off);
            pl += __shfl_xor_sync(0xffffffffu, pl, off);
        }
        float alm = pm * 0.125f;   // / sqrt(64)
        float all = pl * 0.125f;

        float vm0 = Ps[OFF_VMU + lane], vm1 = Ps[OFF_VMU + 32 + lane];
        float vl0 = Ps[OFF_VLS + lane], vl1 = Ps[OFF_VLS + 32 + lane];

        {   // mu online softmax
            float nm = fmaxf(mm, alm);
            float scale = __expf(mm - nm);
            float p = __expf(alm - nm);
            sm = sm * scale + p;
            am0 = am0 * scale + p * vm0;
            am1 = am1 * scale + p * vm1;
            mm = nm;
        }
        {   // logstd online softmax
            float nm = fmaxf(ml, all);
            float scale = __expf(ml - nm);
            float p = __expf(all - nm);
            sl = sl * scale + p;
            al0 = al0 * scale + p * vl0;
            al1 = al1 * scale + p * vl1;
            ml = nm;
        }
    }

    size_t nd = (size_t)n * DDIM;
    float om0 = am0 / (sm + 1e-16f) + Pi[OFF_SMU + lane];
    float om1 = am1 / (sm + 1e-16f) + Pi[OFF_SMU + 32 + lane];
    out[(size_t)i * DDIM + lane]      = om0;
    out[(size_t)i * DDIM + 32 + lane] = om1;

    float ol0 = fminf(al0 / (sl + 1e-16f) + Pi[OFF_SLS + lane], 10.0f);
    float ol1 = fminf(al1 / (sl + 1e-16f) + Pi[OFF_SLS + 32 + lane], 10.0f);
    out[nd + (size_t)i * DDIM + lane]      = ol0;
    out[nd + (size_t)i * DDIM + 32 + lane] = ol1;
}

// ---------------------------------------------------------------------------
// Launch
// ---------------------------------------------------------------------------
extern "C" void kernel_launch(void* const* d_in, const int* in_sizes, int n_in,
                              void* d_out, int out_size) {
    const float* x     = (const float*)d_in[0];
    const void*  ei    = (const void*)d_in[1];
    const float* W_gcn = (const float*)d_in[2];
    const float* b_gcn = (const float*)d_in[3];
    const float* Wq_mu = (const float*)d_in[4];  const float* bq_mu = (const float*)d_in[5];
    const float* Wk_mu = (const float*)d_in[6];  const float* bk_mu = (const float*)d_in[7];
    const float* Wv_mu = (const float*)d_in[8];  const float* bv_mu = (const float*)d_in[9];
    const float* Ws_mu = (const float*)d_in[10]; const float* bs_mu = (const float*)d_in[11];
    const float* Wq_ls = (const float*)d_in[12]; const float* bq_ls = (const float*)d_in[13];
    const float* Wk_ls = (const float*)d_in[14]; const float* bk_ls = (const float*)d_in[15];
    const float* Wv_ls = (const float*)d_in[16]; const float* bv_ls = (const float*)d_in[17];
    const float* Ws_ls = (const float*)d_in[18]; const float* bs_ls = (const float*)d_in[19];
    float* out = (float*)d_out;

    int n = in_sizes[0] / F_IN;      // 50000
    int e = in_sizes[1] / 2;         // 800000

    // 0) dtype detect
    detect_dtype_kernel<<<1, 256>>>((const int*)ei, e);

    // 1) CSR build
    zero_cnt_kernel<<<(n + 255) / 256, 256>>>(n);
    edge_prep_kernel<<<(e + 255) / 256, 256>>>(ei, e, n);
    int nblk = (n + 1023) / 1024;
    scan_pass1_kernel<<<nblk, 1024>>>(n);
    scan_pass2_kernel<<<nblk, 1024>>>(n);
    fill_csr_kernel<<<(e + 255) / 256, 256>>>(e);

    // 2) Pack projection weights (order: qmu,smu,qls,sls,kmu,vmu,kls,vls)
    pack_weights_kernel<<<(HDIM * PDIM + 255) / 256, 256>>>(
        Wq_mu, Ws_mu, Wq_ls, Ws_ls, Wk_mu, Wv_mu, Wk_ls, Wv_ls,
        bq_mu, bs_mu, bq_ls, bs_ls, bk_mu, bv_mu, bk_ls, bv_ls);

    // 3) h0 = x @ W_gcn    [n,256]@[256,128]
    {
        dim3 grid(HDIM / BN, (n + BM - 1) / BM);
        sgemm_xw_kernel<<<grid, 256>>>(x, W_gcn, n);
    }

    // 4) GCN aggregate + bias + LeakyReLU -> h
    gcn_agg_kernel<<<(n + 7) / 8, 256>>>(b_gcn, n);

    // 5) P = h @ Wcat + bcat    [n,128]@[128,512]
    {
        dim3 grid(PDIM / BN, (n + BM - 1) / BM);
        sgemm_proj_kernel<<<grid, 256>>>(n);
    }

    // 6) Fused TransformerConv (mu + logstd) -> out
    transformer_kernel<<<(n + 7) / 8, 256>>>(out, n);
}

// round 5
// speedup vs baseline: 1.8062x; 1.4048x over previous
#include <cuda_runtime.h>
#include <cuda_bf16.h>
#include <math.h>
#include <stdint.h>

// ---------------------------------------------------------------------------
// Problem constants
// ---------------------------------------------------------------------------
#define NMAX 50000
#define EMAX 800000
#define F_IN 256
#define HDIM 128
#define DDIM 64
#define PDIM 512   // 8 projections x 64

// Packed projection offsets within a row of P.
#define OFF_QMU 0
#define OFF_SMU 64
#define OFF_QLS 128
#define OFF_SLS 192
#define OFF_KMU 256
#define OFF_VMU 320
#define OFF_KLS 384
#define OFF_VLS 448

// ---------------------------------------------------------------------------
// Static device scratch
// ---------------------------------------------------------------------------
__device__ int   g_is64;
__device__ int   g_cnt[NMAX];
__device__ int   g_pref[NMAX];
__device__ int   g_bsum[64];
__device__ int   g_rowptr[NMAX + 1];
__device__ int   g_cursor[NMAX];
__device__ int   g_src32[EMAX];
__device__ int   g_dst32[EMAX];
__device__ int   g_csr_src[EMAX];
__device__ float g_dinv[NMAX];
__device__ float g_h0[(size_t)NMAX * HDIM];
__device__ float g_h [(size_t)NMAX * HDIM];
__device__ float g_P [(size_t)NMAX * PDIM];
__device__ float g_Wcat[HDIM * PDIM];
__device__ float g_bcat[PDIM];

// ---------------------------------------------------------------------------
// Edge dtype detection
// ---------------------------------------------------------------------------
__global__ void detect_dtype_kernel(const int* __restrict__ w, int e) {
    __shared__ int s[256];
    int t = threadIdx.x;
    int limit = (e < 256) ? e : 256;
    int nz = 0;
    if (t < limit) nz = (w[2 * t + 1] != 0) ? 1 : 0;
    s[t] = nz;
    __syncthreads();
    for (int o = 128; o; o >>= 1) {
        if (t < o) s[t] += s[t + o];
        __syncthreads();
    }
    if (t == 0) g_is64 = (s[0] == 0) ? 1 : 0;
}

__global__ void zero_cnt_kernel(int n) {
    int i = blockIdx.x * blockDim.x + threadIdx.x;
    if (i < n) g_cnt[i] = 0;
}

__global__ void edge_prep_kernel(const void* __restrict__ ei, int e, int n) {
    int idx = blockIdx.x * blockDim.x + threadIdx.x;
    if (idx >= e) return;
    int s, d;
    if (g_is64) {
        const long long* p = (const long long*)ei;
        s = (int)p[idx];
        d = (int)p[idx + e];
    } else {
        const int* p = (const int*)ei;
        s = p[idx];
        d = p[idx + e];
    }
    s = (s < 0) ? 0 : ((s >= n) ? n - 1 : s);
    d = (d < 0) ? 0 : ((d >= n) ? n - 1 : d);
    g_src32[idx] = s;
    g_dst32[idx] = d;
    atomicAdd(&g_cnt[d], 1);
}

// ---------------------------------------------------------------------------
// Parallel scan (2 passes)
// ---------------------------------------------------------------------------
__global__ void scan_pass1_kernel(int n) {
    __shared__ int s[1024];
    int t = threadIdx.x;
    int i = blockIdx.x * 1024 + t;
    int v = (i < n) ? g_cnt[i] : 0;
    s[t] = v;
    __syncthreads();
    #pragma unroll
    for (int off = 1; off < 1024; off <<= 1) {
        int u = 0;
        if (t >= off) u = s[t - off];
        __syncthreads();
        if (t >= off) s[t] += u;
        __syncthreads();
    }
    if (i < n) g_pref[i] = s[t];
    if (t == 1023) g_bsum[blockIdx.x] = s[t];
}

__global__ void scan_pass2_kernel(int n) {
    __shared__ int sboff;
    int b = blockIdx.x;
    int t = threadIdx.x;
    if (t == 0) {
        int acc = 0;
        for (int j = 0; j < b; ++j) acc += g_bsum[j];
        sboff = acc;
    }
    __syncthreads();
    int i = b * 1024 + t;
    if (i < n) {
        int incl = g_pref[i] + sboff;
        int c = g_cnt[i];
        int excl = incl - c;
        g_rowptr[i] = excl;
        g_cursor[i] = excl;
        g_dinv[i] = rsqrtf((float)(c + 1));
        if (i == n - 1) g_rowptr[n] = incl;
    }
}

__global__ void fill_csr_kernel(int e) {
    int idx = blockIdx.x * blockDim.x + threadIdx.x;
    if (idx >= e) return;
    int d = g_dst32[idx];
    int pos = atomicAdd(&g_cursor[d], 1);
    g_csr_src[pos] = g_src32[idx];
}

// Pointer order matches packed offsets: qmu,smu,qls,sls,kmu,vmu,kls,vls
__global__ void pack_weights_kernel(
    const float* W0, const float* W1, const float* W2, const float* W3,
    const float* W4, const float* W5, const float* W6, const float* W7,
    const float* b0, const float* b1, const float* b2, const float* b3,
    const float* b4, const float* b5, const float* b6, const float* b7) {
    const float* Ws[8] = {W0, W1, W2, W3, W4, W5, W6, W7};
    const float* bs[8] = {b0, b1, b2, b3, b4, b5, b6, b7};
    int idx = blockIdx.x * blockDim.x + threadIdx.x;
    if (idx < HDIM * PDIM) {
        int k = idx / PDIM;
        int j = idx % PDIM;
        int p = j / DDIM;
        int c = j % DDIM;
        g_Wcat[idx] = Ws[p][k * DDIM + c];
    }
    if (idx < PDIM) {
        g_bcat[idx] = bs[idx / DDIM][idx % DDIM];
    }
}

// ---------------------------------------------------------------------------
// TF32 tensor-core GEMM: C[M,NC] = A[M,K] @ B[K,NC] (+bias)
// Block 128x128x32, 256 threads = 8 warps (2x4), warp tile 64x32.
// mma.sync.aligned.m16n8k8.row.col.f32.tf32.tf32.f32
// K % 32 == 0, NC % 128 == 0, M ragged.
// ---------------------------------------------------------------------------
#define TM 128
#define TN 128
#define TK 32
#define SROW 136   // 128 + 8 pad words -> conflict-free fragment LDS

__device__ __forceinline__ uint32_t f2tf32(float v) {
    uint32_t o;
    asm volatile("cvt.rna.tf32.f32 %0, %1;" : "=r"(o) : "f"(v));
    return o;
}

__device__ __forceinline__ void mma_tf32(float* c,
    uint32_t a0, uint32_t a1, uint32_t a2, uint32_t a3,
    uint32_t b0, uint32_t b1) {
    asm volatile(
        "mma.sync.aligned.m16n8k8.row.col.f32.tf32.tf32.f32 "
        "{%0,%1,%2,%3}, {%4,%5,%6,%7}, {%8,%9}, {%0,%1,%2,%3};"
        : "+f"(c[0]), "+f"(c[1]), "+f"(c[2]), "+f"(c[3])
        : "r"(a0), "r"(a1), "r"(a2), "r"(a3), "r"(b0), "r"(b1));
}

__device__ __forceinline__ void gemm_tf32_core(
    const float* __restrict__ A, const float* __restrict__ B,
    const float* __restrict__ bias, float* __restrict__ C,
    int M, int K, int NC) {
    __shared__ uint32_t As[TK][SROW];   // col-major: As[k][m], tf32 bits
    __shared__ uint32_t Bs[TK][SROW];   // row-major: Bs[k][n], tf32 bits

    int t = threadIdx.x;
    int lane = t & 31;
    int warp = t >> 5;
    int wm = warp >> 2;        // 0..1
    int wn = warp & 3;         // 0..3
    int g  = lane >> 2;        // groupID 0..7
    int tg = lane & 3;         // threadID in group 0..3

    int rowBlock = blockIdx.y * TM;
    int colBlock = blockIdx.x * TN;

    float c[4][4][4];
    #pragma unroll
    for (int i = 0; i < 4; ++i)
        #pragma unroll
        for (int j = 0; j < 4; ++j)
            #pragma unroll
            for (int k = 0; k < 4; ++k) c[i][j][k] = 0.f;

    for (int k0 = 0; k0 < K; k0 += TK) {
        // A tile: TM x TK = 4096 floats = 1024 float4; 4 per thread.
        // Transposed store with cvt to tf32.
        #pragma unroll
        for (int l = 0; l < 4; ++l) {
            int lin = t + l * 256;
            int ar = lin >> 3;            // 0..127 (m)
            int ac = (lin & 7) << 2;      // 0..28 (k)
            float4 v = make_float4(0.f, 0.f, 0.f, 0.f);
            int grow = rowBlock + ar;
            if (grow < M)
                v = *(const float4*)&A[(size_t)grow * K + k0 + ac];
            As[ac + 0][ar] = f2tf32(v.x);
            As[ac + 1][ar] = f2tf32(v.y);
            As[ac + 2][ar] = f2tf32(v.z);
            As[ac + 3][ar] = f2tf32(v.w);
        }
        // B tile: TK x TN = 4096 floats; 4 float4 per thread, row-major.
        #pragma unroll
        for (int l = 0; l < 4; ++l) {
            int lin = t + l * 256;
            int br = lin >> 5;            // 0..31 (k)
            int bc = (lin & 31) << 2;     // 0..124 (n)
            float4 v = *(const float4*)&B[(size_t)(k0 + br) * NC + colBlock + bc];
            uint4 u;
            u.x = f2tf32(v.x); u.y = f2tf32(v.y);
            u.z = f2tf32(v.z); u.w = f2tf32(v.w);
            *(uint4*)&Bs[br][bc] = u;
        }
        __syncthreads();

        #pragma unroll
        for (int ks = 0; ks < TK / 8; ++ks) {
            int kr = ks * 8 + tg;
            uint32_t a[4][4], b[4][2];
            #pragma unroll
            for (int mt = 0; mt < 4; ++mt) {
                int mb = wm * 64 + mt * 16 + g;
                a[mt][0] = As[kr][mb];
                a[mt][1] = As[kr][mb + 8];
                a[mt][2] = As[kr + 4][mb];
                a[mt][3] = As[kr + 4][mb + 8];
            }
            #pragma unroll
            for (int nt = 0; nt < 4; ++nt) {
                int nb = wn * 32 + nt * 8 + g;
                b[nt][0] = Bs[kr][nb];
                b[nt][1] = Bs[kr + 4][nb];
            }
            #pragma unroll
            for (int mt = 0; mt < 4; ++mt)
                #pragma unroll
                for (int nt = 0; nt < 4; ++nt)
                    mma_tf32(c[mt][nt], a[mt][0], a[mt][1], a[mt][2], a[mt][3],
                             b[nt][0], b[nt][1]);
        }
        __syncthreads();
    }

    // Epilogue: c0/c1 -> (row g, cols 2tg,2tg+1), c2/c3 -> row g+8.
    #pragma unroll
    for (int mt = 0; mt < 4; ++mt) {
        #pragma unroll
        for (int nt = 0; nt < 4; ++nt) {
            int col = colBlock + wn * 32 + nt * 8 + tg * 2;
            float b0 = 0.f, b1 = 0.f;
            if (bias) { b0 = bias[col]; b1 = bias[col + 1]; }
            int row0 = rowBlock + wm * 64 + mt * 16 + g;
            if (row0 < M) {
                float2 o = make_float2(c[mt][nt][0] + b0, c[mt][nt][1] + b1);
                *(float2*)&C[(size_t)row0 * NC + col] = o;
            }
            int row1 = row0 + 8;
            if (row1 < M) {
                float2 o = make_float2(c[mt][nt][2] + b0, c[mt][nt][3] + b1);
                *(float2*)&C[(size_t)row1 * NC + col] = o;
            }
        }
    }
}

__global__ __launch_bounds__(256) void gemm_xw_kernel(
    const float* __restrict__ A, const float* __restrict__ B, int M) {
    gemm_tf32_core(A, B, nullptr, g_h0, M, F_IN, HDIM);
}

__global__ __launch_bounds__(256) void gemm_proj_kernel(int M) {
    gemm_tf32_core(g_h, g_Wcat, g_bcat, g_P, M, HDIM, PDIM);
}

// ---------------------------------------------------------------------------
// GCN aggregate: one warp per node.
// ---------------------------------------------------------------------------
__global__ void gcn_agg_kernel(const float* __restrict__ bias, int n) {
    int warp = (blockIdx.x * blockDim.x + threadIdx.x) >> 5;
    int lane = threadIdx.x & 31;
    if (warp >= n) return;
    int i = warp;
    float di = g_dinv[i];

    float4 acc = make_float4(0.f, 0.f, 0.f, 0.f);
    int e0 = g_rowptr[i], e1 = g_rowptr[i + 1];
    for (int e = e0; e < e1; ++e) {
        int src = g_csr_src[e];
        float w = g_dinv[src] * di;
        float4 v = *(const float4*)&g_h0[(size_t)src * HDIM + lane * 4];
        acc.x = fmaf(w, v.x, acc.x);
        acc.y = fmaf(w, v.y, acc.y);
        acc.z = fmaf(w, v.z, acc.z);
        acc.w = fmaf(w, v.w, acc.w);
    }
    {   // self loop
        float w = di * di;
        float4 v = *(const float4*)&g_h0[(size_t)i * HDIM + lane * 4];
        acc.x = fmaf(w, v.x, acc.x);
        acc.y = fmaf(w, v.y, acc.y);
        acc.z = fmaf(w, v.z, acc.z);
        acc.w = fmaf(w, v.w, acc.w);
    }
    float4 bb = *(const float4*)&bias[lane * 4];
    acc.x += bb.x; acc.y += bb.y; acc.z += bb.z; acc.w += bb.w;
    acc.x = (acc.x >= 0.f) ? acc.x : 0.01f * acc.x;
    acc.y = (acc.y >= 0.f) ? acc.y : 0.01f * acc.y;
    acc.z = (acc.z >= 0.f) ? acc.z : 0.01f * acc.z;
    acc.w = (acc.w >= 0.f) ? acc.w : 0.01f * acc.w;
    *(float4*)&g_h[(size_t)i * HDIM + lane * 4] = acc;
}

// ---------------------------------------------------------------------------
// Fused TransformerConv (mu + logstd): one warp per dst node, online softmax.
// ---------------------------------------------------------------------------
__global__ void transformer_kernel(float* __restrict__ out, int n) {
    int warp = (blockIdx.x * blockDim.x + threadIdx.x) >> 5;
    int lane = threadIdx.x & 31;
    if (warp >= n) return;
    int i = warp;
    const float* Pi = &g_P[(size_t)i * PDIM];

    float qm0 = Pi[OFF_QMU + lane], qm1 = Pi[OFF_QMU + 32 + lane];
    float ql0 = Pi[OFF_QLS + lane], ql1 = Pi[OFF_QLS + 32 + lane];

    float mm = -INFINITY, ml = -INFINITY;
    float sm = 0.f, sl = 0.f;
    float am0 = 0.f, am1 = 0.f, al0 = 0.f, al1 = 0.f;

    int e0 = g_rowptr[i], e1 = g_rowptr[i + 1];
    for (int e = e0; e < e1; ++e) {
        int src = g_csr_src[e];
        const float* Ps = &g_P[(size_t)src * PDIM];

        float pm = qm0 * Ps[OFF_KMU + lane] + qm1 * Ps[OFF_KMU + 32 + lane];
        float pl = ql0 * Ps[OFF_KLS + lane] + ql1 * Ps[OFF_KLS + 32 + lane];
        #pragma unroll
        for (int off = 16; off; off >>= 1) {
            pm += __shfl_xor_sync(0xffffffffu, pm, off);
            pl += __shfl_xor_sync(0xffffffffu, pl, off);
        }
        float alm = pm * 0.125f;
        float all = pl * 0.125f;

        float vm0 = Ps[OFF_VMU + lane], vm1 = Ps[OFF_VMU + 32 + lane];
        float vl0 = Ps[OFF_VLS + lane], vl1 = Ps[OFF_VLS + 32 + lane];

        {
            float nm = fmaxf(mm, alm);
            float scale = __expf(mm - nm);
            float p = __expf(alm - nm);
            sm = sm * scale + p;
            am0 = am0 * scale + p * vm0;
            am1 = am1 * scale + p * vm1;
            mm = nm;
        }
        {
            float nm = fmaxf(ml, all);
            float scale = __expf(ml - nm);
            float p = __expf(all - nm);
            sl = sl * scale + p;
            al0 = al0 * scale + p * vl0;
            al1 = al1 * scale + p * vl1;
            ml = nm;
        }
    }

    size_t nd = (size_t)n * DDIM;
    float om0 = am0 / (sm + 1e-16f) + Pi[OFF_SMU + lane];
    float om1 = am1 / (sm + 1e-16f) + Pi[OFF_SMU + 32 + lane];
    out[(size_t)i * DDIM + lane]      = om0;
    out[(size_t)i * DDIM + 32 + lane] = om1;

    float ol0 = fminf(al0 / (sl + 1e-16f) + Pi[OFF_SLS + lane], 10.0f);
    float ol1 = fminf(al1 / (sl + 1e-16f) + Pi[OFF_SLS + 32 + lane], 10.0f);
    out[nd + (size_t)i * DDIM + lane]      = ol0;
    out[nd + (size_t)i * DDIM + 32 + lane] = ol1;
}

// ---------------------------------------------------------------------------
// Launch
// ---------------------------------------------------------------------------
extern "C" void kernel_launch(void* const* d_in, const int* in_sizes, int n_in,
                              void* d_out, int out_size) {
    const float* x     = (const float*)d_in[0];
    const void*  ei    = (const void*)d_in[1];
    const float* W_gcn = (const float*)d_in[2];
    const float* b_gcn = (const float*)d_in[3];
    const float* Wq_mu = (const float*)d_in[4];  const float* bq_mu = (const float*)d_in[5];
    const float* Wk_mu = (const float*)d_in[6];  const float* bk_mu = (const float*)d_in[7];
    const float* Wv_mu = (const float*)d_in[8];  const float* bv_mu = (const float*)d_in[9];
    const float* Ws_mu = (const float*)d_in[10]; const float* bs_mu = (const float*)d_in[11];
    const float* Wq_ls = (const float*)d_in[12]; const float* bq_ls = (const float*)d_in[13];
    const float* Wk_ls = (const float*)d_in[14]; const float* bk_ls = (const float*)d_in[15];
    const float* Wv_ls = (const float*)d_in[16]; const float* bv_ls = (const float*)d_in[17];
    const float* Ws_ls = (const float*)d_in[18]; const float* bs_ls = (const float*)d_in[19];
    float* out = (float*)d_out;

    int n = in_sizes[0] / F_IN;      // 50000
    int e = in_sizes[1] / 2;         // 800000

    // 0) dtype detect
    detect_dtype_kernel<<<1, 256>>>((const int*)ei, e);

    // 1) CSR build
    zero_cnt_kernel<<<(n + 255) / 256, 256>>>(n);
    edge_prep_kernel<<<(e + 255) / 256, 256>>>(ei, e, n);
    int nblk = (n + 1023) / 1024;
    scan_pass1_kernel<<<nblk, 1024>>>(n);
    scan_pass2_kernel<<<nblk, 1024>>>(n);
    fill_csr_kernel<<<(e + 255) / 256, 256>>>(e);

    // 2) Pack projection weights (qmu,smu,qls,sls,kmu,vmu,kls,vls)
    pack_weights_kernel<<<(HDIM * PDIM + 255) / 256, 256>>>(
        Wq_mu, Ws_mu, Wq_ls, Ws_ls, Wk_mu, Wv_mu, Wk_ls, Wv_ls,
        bq_mu, bs_mu, bq_ls, bs_ls, bk_mu, bv_mu, bk_ls, bv_ls);

    // 3) h0 = x @ W_gcn    [n,256]@[256,128]  (tf32 MMA)
    {
        dim3 grid(HDIM / TN, (n + TM - 1) / TM);
        gemm_xw_kernel<<<grid, 256>>>(x, W_gcn, n);
    }

    // 4) GCN aggregate + bias + LeakyReLU -> h
    gcn_agg_kernel<<<(n + 7) / 8, 256>>>(b_gcn, n);

    // 5) P = h @ Wcat + bcat    [n,128]@[128,512]  (tf32 MMA)
    {
        dim3 grid(PDIM / TN, (n + TM - 1) / TM);
        gemm_proj_kernel<<<grid, 256>>>(n);
    }

    // 6) Fused TransformerConv (mu + logstd) -> out
    transformer_kernel<<<(n + 7) / 8, 256>>>(out, n);
}